// round 5
// baseline (speedup 1.0000x reference)
#include <cuda_runtime.h>
#include <cuda_bf16.h>
#include <math.h>

// Fixed problem shape: F=200000, B=4, V=100000.
#define FMAX 200000
#define BMAX 4
#define VMAX 100000

// Packed per-face record, padded to 128B (one L2 line), 128B-aligned.
// float layout (float4 chunks 0..5 used, 6..7 pad):
//  0..5  : vt0.u vt0.v vt1.u vt1.v vt2.u vt2.v
//  6..14 : vn0.xyz vn1.xyz vn2.xyz
// 15..23 : v0.xyz  v1.xyz  v2.xyz
__device__ __align__(128) float4 g_packed[FMAX * 8];
// Per (b,f): {1/z0, 1/z1, 1/z2, 0}
__device__ float4 g_invfz[BMAX * FMAX];
// float4-expanded vertex attribute tables (single LDG.128 per gather)
__device__ float4 g_verts4[VMAX];
__device__ float4 g_vns4[VMAX];

// Grid barrier state (generation counter; replays keep incrementing g_release).
__device__ unsigned g_arrive = 0;
__device__ unsigned g_release = 0;

#define BLK   128
#define BPSM  7
#define NBLK  (148 * BPSM)   // 1036 — co-resident on 148 SMs at 7/SM (and on 152)
#define PF    40             // faces per pack tile (120 gather threads)

__device__ __forceinline__ void grid_barrier() {
    __syncthreads();
    if (threadIdx.x == 0) {
        __threadfence();
        unsigned gen = atomicAdd(&g_release, 0u);
        unsigned t = atomicAdd(&g_arrive, 1u);
        if (t == NBLK - 1) {
            g_arrive = 0;
            __threadfence();
            atomicExch(&g_release, gen + 1u);
        } else {
            while (atomicAdd(&g_release, 0u) == gen) { __nanosleep(64); }
        }
        __threadfence();
    }
    __syncthreads();
}

__global__ __launch_bounds__(BLK, BPSM) void raster_fused_kernel(
        const float* __restrict__ verts,
        const float* __restrict__ vts,
        const float* __restrict__ vns,
        const int* __restrict__ f_vt,
        const int* __restrict__ f_vn,
        const int* __restrict__ f_v,
        const float* __restrict__ fuvz,
        const int* __restrict__ fidx_map,
        const float* __restrict__ depth,
        const float* __restrict__ weight,
        const float* __restrict__ pose,
        float* __restrict__ out,
        int V, int F, int B, int HW, int total) {
    // Shared across phases: B uses first 320 float4; C uses 7/pixel + fidx.
    __shared__ float4 s_rec[BLK * 7];
    __shared__ int s_fidx[BLK];

    int tid = threadIdx.x;
    int nthreads = NBLK * BLK;
    int gtid = blockIdx.x * BLK + tid;
    int BF = B * F;

    // ---------------- Phase A: expand verts/vns + inv-fz (streaming) ----------
    for (int i = gtid; i < V + BF; i += nthreads) {
        if (i < V) {
            g_verts4[i] = make_float4(__ldcs(&verts[3 * i]), __ldcs(&verts[3 * i + 1]),
                                      __ldcs(&verts[3 * i + 2]), 0.0f);
            g_vns4[i]   = make_float4(__ldcs(&vns[3 * i]), __ldcs(&vns[3 * i + 1]),
                                      __ldcs(&vns[3 * i + 2]), 0.0f);
        } else {
            int j = i - V;
            const float* sp = fuvz + (size_t)j * 9;
            float4 o;
            o.x = 1.0f / __ldcs(&sp[2]);
            o.y = 1.0f / __ldcs(&sp[5]);
            o.z = 1.0f / __ldcs(&sp[8]);
            o.w = 0.0f;
            g_invfz[j] = o;
        }
    }
    grid_barrier();

    // ---------------- Phase B: pack face records --------------------------------
    {
        int ntiles = (F + PF - 1) / PF;   // 5000 for F=200000
        float* s = (float*)s_rec;
        for (int t = blockIdx.x; t < ntiles; t += NBLK) {
            int fbase = t * PF;
            if (tid < PF * 3) {
                int gi = fbase * 3 + tid;           // coalesced corner index
                int fl = tid / 3, k = tid - fl * 3;
                int it  = __ldg(&f_vt[gi]);
                int in_ = __ldg(&f_vn[gi]);
                int iv  = __ldg(&f_v[gi]);
                float2 t2 = __ldg((const float2*)vts + it);
                float4 n4 = __ldg(&g_vns4[in_]);
                float4 v4 = __ldg(&g_verts4[iv]);
                float* rec = s + fl * 32;
                rec[k * 2 + 0] = t2.x;  rec[k * 2 + 1] = t2.y;
                rec[6 + 3 * k + 0] = n4.x; rec[6 + 3 * k + 1] = n4.y; rec[6 + 3 * k + 2] = n4.z;
                rec[15 + 3 * k + 0] = v4.x; rec[15 + 3 * k + 1] = v4.y; rec[15 + 3 * k + 2] = v4.z;
            }
            __syncthreads();
            float4* dst = g_packed + (size_t)fbase * 8;
            int nf4 = PF * 8;                       // 320
#pragma unroll
            for (int itn = 0; itn < 3; itn++) {
                int e = itn * BLK + tid;
                if (e < nf4) dst[e] = s_rec[e];
            }
            __syncthreads();
        }
    }
    grid_barrier();

    // ---------------- Phase C: per-pixel main pass ------------------------------
    {
        int ntiles = (total + BLK - 1) / BLK;       // 8192
        for (int t = blockIdx.x; t < ntiles; t += NBLK) {
            int gid = t * BLK + tid;
            bool active = (gid < total);
            int b = (t * BLK) / HW;                 // uniform per tile (BLK | HW)

            int f = 0;
            float d = 0.f, w0 = 0.f, w1 = 0.f, w2 = 0.f;
            float4 iz = make_float4(0.f, 0.f, 0.f, 0.f);
            if (active) {
                f  = __ldcs(&fidx_map[gid]);
                d  = __ldcs(&depth[gid]);
                w0 = __ldcs(&weight[gid * 3 + 0]);
                w1 = __ldcs(&weight[gid * 3 + 1]);
                w2 = __ldcs(&weight[gid * 3 + 2]);
                iz = g_invfz[b * F + f];
            }
            s_fidx[tid] = f;
            __syncthreads();

            // Cooperative record gather: consecutive lanes fetch consecutive
            // chunks of the same 128B-aligned record (~5-6 lines/LDG vs 32).
#pragma unroll
            for (int i = 0; i < 6; i++) {
                int id = i * BLK + tid;
                int p = id / 6;
                int c = id - p * 6;
                int fp = s_fidx[p];
                s_rec[p * 7 + c] = g_packed[(size_t)fp * 8 + c];
            }
            __syncthreads();

            float vals[14];
#pragma unroll
            for (int j = 0; j < 14; j++) vals[j] = 0.0f;

            if (active) {
                const float4* rp = s_rec + tid * 7;
                float4 r0 = rp[0], r1 = rp[1], r2 = rp[2];
                float4 r3 = rp[3], r4 = rp[4], r5 = rp[5];

                float c0 = iz.x * w0 * d;
                float c1 = iz.y * w1 * d;
                float c2 = iz.z * w2 * d;

                float u = r0.x * c0 + r0.z * c1 + r1.x * c2;
                float v = r0.y * c0 + r0.w * c1 + r1.y * c2;
                u = u - floorf(u);
                v = v - floorf(v);

                float nx = r1.z * c0 + r2.y * c1 + r3.x * c2;
                float ny = r1.w * c0 + r2.z * c1 + r3.y * c2;
                float nz = r2.x * c0 + r2.w * c1 + r3.z * c2;
                float nl = sqrtf(nx * nx + ny * ny + nz * nz);
                float inl = 1.0f / fmaxf(nl, 1e-12f);
                float Nx = nx * inl, Ny = ny * inl, Nz = nz * inl;

                float px = r3.w * c0 + r4.z * c1 + r5.y * c2;
                float py = r4.x * c0 + r4.w * c1 + r5.z * c2;
                float pz = r4.y * c0 + r5.x * c1 + r5.w * c2;

                const float* P = pose + b * 16;
                float R00 = __ldg(&P[0]), R01 = __ldg(&P[1]), R02 = __ldg(&P[2]),  t0 = __ldg(&P[3]);
                float R10 = __ldg(&P[4]), R11 = __ldg(&P[5]), R12 = __ldg(&P[6]),  t1 = __ldg(&P[7]);
                float R20 = __ldg(&P[8]), R21 = __ldg(&P[9]), R22 = __ldg(&P[10]), t2 = __ldg(&P[11]);

                float mx = R00 * Nx + R01 * Ny + R02 * Nz;
                float my = R10 * Nx + R11 * Ny + R12 * Nz;
                float mz = R20 * Nx + R21 * Ny + R22 * Nz;
                float ml = sqrtf(mx * mx + my * my + mz * mz);
                float iml = 1.0f / fmaxf(ml, 1e-12f);
                mx *= iml; my *= iml; mz *= iml;

                float qx = R00 * px + R01 * py + R02 * pz + t0;
                float qy = R10 * px + R11 * py + R12 * pz + t1;
                float qz = R20 * px + R21 * py + R22 * pz + t2;

                vals[0] = u;   vals[1] = v;
                vals[2] = Nx;  vals[3] = Ny;  vals[4] = Nz;
                vals[5] = mx;  vals[6] = my;  vals[7] = mz;
                vals[8] = px;  vals[9] = py;  vals[10] = pz;
                vals[11] = qx; vals[12] = qy; vals[13] = qz;
            }

            // Reuse s_rec as float staging for coalesced output stores.
            __syncthreads();
            float* sm = (float*)s_rec;
#pragma unroll
            for (int j = 0; j < 14; j++) sm[tid * 14 + j] = vals[j];
            __syncthreads();

            size_t blk_base = (size_t)t * BLK * 14;
            const float4* sm4 = (const float4*)sm;
            float4* out4 = (float4*)(out + blk_base);
            int nfloat4 = (BLK * 14) / 4;            // 448
            size_t limit4 = ((size_t)total * 14 - blk_base) / 4;
#pragma unroll
            for (int idx = 0; idx < 4; idx++) {
                int e = idx * BLK + tid;
                if (e < nfloat4 && (size_t)e < limit4)
                    __stcs(&out4[e], sm4[e]);
            }
            __syncthreads();   // protect smem reuse across tile iterations
        }
    }
}

extern "C" void kernel_launch(void* const* d_in, const int* in_sizes, int n_in,
                              void* d_out, int out_size) {
    const float* vertices = (const float*)d_in[0];   // (1,V,3)
    const float* vt       = (const float*)d_in[1];   // (1,V,2)
    const float* vn       = (const float*)d_in[2];   // (1,V,3)
    const int*   f_vt     = (const int*)d_in[3];     // (1,F,3)
    const int*   f_vn     = (const int*)d_in[4];     // (1,F,3)
    const int*   f_v      = (const int*)d_in[5];     // (1,F,3)
    const float* pose     = (const float*)d_in[6];   // (B,4,4)
    const float* depth    = (const float*)d_in[7];   // (B,H,W)
    const int*   fim      = (const int*)d_in[8];     // (B,H,W)
    const float* wm       = (const float*)d_in[9];   // (B,H,W,3)
    // d_in[10] = v_uvz: dead code in reference
    const float* fuvz     = (const float*)d_in[11];  // (B,F,3,3)

    int V   = in_sizes[0] / 3;
    int F   = in_sizes[3] / 3;
    int B   = in_sizes[6] / 16;
    int BHW = in_sizes[7];
    int HW  = BHW / B;

    raster_fused_kernel<<<NBLK, BLK>>>(vertices, vt, vn, f_vt, f_vn, f_v,
                                       fuvz, fim, depth, wm, pose,
                                       (float*)d_out, V, F, B, HW, BHW);
}

// round 8
// speedup vs baseline: 1.4096x; 1.4096x over previous
#include <cuda_runtime.h>
#include <cuda_fp16.h>
#include <math.h>

// Fixed problem shape: F=200000, B=4, V=100000.
#define FMAX 200000
#define BMAX 4
#define VMAX 100000

// Mixed-precision 64B per-face record (4 uint4 chunks), 128B-array-aligned.
// bytes  0..23 : vt as fp32  [vt0.u vt0.v vt1.u vt1.v vt2.u vt2.v]
// bytes 24..41 : vn as fp16  [vn0.xyz vn1.xyz vn2.xyz]   (half idx 12..20)
// bytes 42..59 : v  as fp16  [v0.xyz  v1.xyz  v2.xyz ]   (half idx 21..29)
// bytes 60..63 : pad                                      (half idx 30..31)
__device__ __align__(128) uint4 g_packed[FMAX * 4];
// Per (b,f): {1/z0, 1/z1, 1/z2, 0} fp32
__device__ float4 g_invfz[BMAX * FMAX];
// fp32-expanded vertex attribute tables (one LDG.128 per gather in pack)
__device__ float4 g_verts4[VMAX];
__device__ float4 g_vns4[VMAX];

// ---------- pass 1: prep (vertex expand + inv-fz), pure streaming ----------
__global__ __launch_bounds__(256) void prep_kernel(
        const float* __restrict__ verts,
        const float* __restrict__ vns,
        const float* __restrict__ fuvz,
        int V, int BF) {
    int i = blockIdx.x * 256 + threadIdx.x;
    if (i < V) {
        g_verts4[i] = make_float4(__ldcs(&verts[3 * i]), __ldcs(&verts[3 * i + 1]),
                                  __ldcs(&verts[3 * i + 2]), 0.0f);
        g_vns4[i]   = make_float4(__ldcs(&vns[3 * i]), __ldcs(&vns[3 * i + 1]),
                                  __ldcs(&vns[3 * i + 2]), 0.0f);
    } else {
        int j = i - V;
        if (j < BF) {
            const float* sp = fuvz + (size_t)j * 9;
            float4 o;
            o.x = 1.0f / __ldcs(&sp[2]);
            o.y = 1.0f / __ldcs(&sp[5]);
            o.z = 1.0f / __ldcs(&sp[8]);
            o.w = 0.0f;
            g_invfz[j] = o;
        }
    }
}

// ---------- pass 2: pack mixed-precision face records ----------
#define PF 64   // faces per block (192 gather lanes of 256)
__global__ __launch_bounds__(256) void pack_kernel(
        const float* __restrict__ vts,
        const int* __restrict__ f_vt,
        const int* __restrict__ f_vn,
        const int* __restrict__ f_v,
        int F) {
    __shared__ float s_f[PF * 16];           // PF x 64B records
    int tid = threadIdx.x;
    int fbase = blockIdx.x * PF;
    if (tid < PF * 3) {
        int gi = fbase * 3 + tid;            // coalesced corner index
        int fl = tid / 3, k = tid - fl * 3;
        bool ok = (fbase + fl) < F;
        int it  = ok ? __ldg(&f_vt[gi]) : 0;
        int in_ = ok ? __ldg(&f_vn[gi]) : 0;
        int iv  = ok ? __ldg(&f_v[gi])  : 0;
        float2 t2 = __ldg((const float2*)vts + it);
        float4 n4 = __ldg(&g_vns4[in_]);
        float4 v4 = __ldg(&g_verts4[iv]);
        float*  rf = s_f + fl * 16;
        __half* rh = (__half*)rf;
        rf[2 * k + 0] = t2.x;
        rf[2 * k + 1] = t2.y;
        rh[12 + 3 * k + 0] = __float2half_rn(n4.x);
        rh[12 + 3 * k + 1] = __float2half_rn(n4.y);
        rh[12 + 3 * k + 2] = __float2half_rn(n4.z);
        rh[21 + 3 * k + 0] = __float2half_rn(v4.x);
        rh[21 + 3 * k + 1] = __float2half_rn(v4.y);
        rh[21 + 3 * k + 2] = __float2half_rn(v4.z);
        if (k == 0) { rh[30] = __float2half_rn(0.f); rh[31] = __float2half_rn(0.f); }
    }
    __syncthreads();
    // PF*4 = 256 uint4 chunks -> one coalesced store per thread.
    const uint4* s4 = (const uint4*)s_f;
    size_t di = (size_t)fbase * 4 + tid;
    if (di < (size_t)FMAX * 4)
        g_packed[di] = s4[tid];
}

// ---------- pass 3: main per-pixel pass ----------
#define BLK 256

__global__ __launch_bounds__(BLK) void raster_main_kernel(
        const int* __restrict__ fidx_map,
        const float* __restrict__ depth,
        const float* __restrict__ weight,
        const float* __restrict__ pose,
        float* __restrict__ out,
        int HW, int F, int total) {
    __shared__ float sm[BLK * 14];

    int tid = threadIdx.x;
    int gid = blockIdx.x * BLK + tid;
    bool active = (gid < total);
    int b = (blockIdx.x * BLK) / HW;          // uniform per block (BLK | HW)

    float vals[14];
#pragma unroll
    for (int j = 0; j < 14; j++) vals[j] = 0.0f;

    if (active) {
        int f = __ldcs(&fidx_map[gid]);
        float d  = __ldcs(&depth[gid]);
        float w0 = __ldcs(&weight[gid * 3 + 0]);
        float w1 = __ldcs(&weight[gid * 3 + 1]);
        float w2 = __ldcs(&weight[gid * 3 + 2]);

        // 5 divergent gathers total: iz + 4 record chunks.
        float4 iz = __ldg(&g_invfz[b * F + f]);
        const uint4* rec4 = g_packed + (size_t)f * 4;
        uint4 q0 = __ldg(&rec4[0]);
        uint4 q1 = __ldg(&rec4[1]);
        uint4 q2 = __ldg(&rec4[2]);
        uint4 q3 = __ldg(&rec4[3]);

        // fp32 vt: words 0..5 of record
        float vt00 = __uint_as_float(q0.x);
        float vt01 = __uint_as_float(q0.y);
        float vt10 = __uint_as_float(q0.z);
        float vt11 = __uint_as_float(q0.w);
        float vt20 = __uint_as_float(q1.x);
        float vt21 = __uint_as_float(q1.y);

        // fp16 vn + v: words 6..15 -> 20 halves (18 used)
        float h[20];
        {
            unsigned int w[10] = {q1.z, q1.w,
                                  q2.x, q2.y, q2.z, q2.w,
                                  q3.x, q3.y, q3.z, q3.w};
#pragma unroll
            for (int i = 0; i < 10; i++) {
                float2 f2 = __half22float2(*(const __half2*)&w[i]);
                h[2 * i] = f2.x; h[2 * i + 1] = f2.y;
            }
        }
        // h[0..8]  = vn0.xyz vn1.xyz vn2.xyz  (half idx 12..20)
        // h[9..17] = v0.xyz  v1.xyz  v2.xyz   (half idx 21..29)

        float c0 = iz.x * w0 * d;
        float c1 = iz.y * w1 * d;
        float c2 = iz.z * w2 * d;

        // uv (full fp32)
        float u = vt00 * c0 + vt10 * c1 + vt20 * c2;
        float v = vt01 * c0 + vt11 * c1 + vt21 * c2;
        u = u - floorf(u);
        v = v - floorf(v);

        // normal blend + normalize
        float nx = h[0] * c0 + h[3] * c1 + h[6] * c2;
        float ny = h[1] * c0 + h[4] * c1 + h[7] * c2;
        float nz = h[2] * c0 + h[5] * c1 + h[8] * c2;
        float nl = sqrtf(nx * nx + ny * ny + nz * nz);
        float inl = 1.0f / fmaxf(nl, 1e-12f);
        float Nx = nx * inl, Ny = ny * inl, Nz = nz * inl;

        // position blend
        float px = h[9]  * c0 + h[12] * c1 + h[15] * c2;
        float py = h[10] * c0 + h[13] * c1 + h[16] * c2;
        float pz = h[11] * c0 + h[14] * c1 + h[17] * c2;

        // pose (b block-uniform -> broadcast loads)
        const float* P = pose + b * 16;
        float R00 = __ldg(&P[0]), R01 = __ldg(&P[1]), R02 = __ldg(&P[2]),  t0 = __ldg(&P[3]);
        float R10 = __ldg(&P[4]), R11 = __ldg(&P[5]), R12 = __ldg(&P[6]),  t1 = __ldg(&P[7]);
        float R20 = __ldg(&P[8]), R21 = __ldg(&P[9]), R22 = __ldg(&P[10]), t2 = __ldg(&P[11]);

        float mx = R00 * Nx + R01 * Ny + R02 * Nz;
        float my = R10 * Nx + R11 * Ny + R12 * Nz;
        float mz = R20 * Nx + R21 * Ny + R22 * Nz;
        float ml = sqrtf(mx * mx + my * my + mz * mz);
        float iml = 1.0f / fmaxf(ml, 1e-12f);
        mx *= iml; my *= iml; mz *= iml;

        float qx = R00 * px + R01 * py + R02 * pz + t0;
        float qy = R10 * px + R11 * py + R12 * pz + t1;
        float qz = R20 * px + R21 * py + R22 * pz + t2;

        vals[0] = u;   vals[1] = v;
        vals[2] = Nx;  vals[3] = Ny;  vals[4] = Nz;
        vals[5] = mx;  vals[6] = my;  vals[7] = mz;
        vals[8] = px;  vals[9] = py;  vals[10] = pz;
        vals[11] = qx; vals[12] = qy; vals[13] = qz;
    }

    // Stage to smem, then coalesced float4 streaming stores.
#pragma unroll
    for (int j = 0; j < 14; j++) sm[tid * 14 + j] = vals[j];
    __syncthreads();

    size_t blk_base = (size_t)blockIdx.x * BLK * 14;
    const float4* sm4 = (const float4*)sm;
    float4* out4 = (float4*)(out + blk_base);
    int nfloat4 = (BLK * 14) / 4;                      // 896
    size_t limit4 = ((size_t)total * 14 - blk_base) / 4;
#pragma unroll
    for (int idx = 0; idx < nfloat4 / BLK + 1; idx++) {
        int e = idx * BLK + tid;
        if (e < nfloat4 && (size_t)e < limit4)
            __stcs(&out4[e], sm4[e]);
    }
}

extern "C" void kernel_launch(void* const* d_in, const int* in_sizes, int n_in,
                              void* d_out, int out_size) {
    const float* vertices = (const float*)d_in[0];   // (1,V,3)
    const float* vt       = (const float*)d_in[1];   // (1,V,2)
    const float* vn       = (const float*)d_in[2];   // (1,V,3)
    const int*   f_vt     = (const int*)d_in[3];     // (1,F,3)
    const int*   f_vn     = (const int*)d_in[4];     // (1,F,3)
    const int*   f_v      = (const int*)d_in[5];     // (1,F,3)
    const float* pose     = (const float*)d_in[6];   // (B,4,4)
    const float* depth    = (const float*)d_in[7];   // (B,H,W)
    const int*   fim      = (const int*)d_in[8];     // (B,H,W)
    const float* wm       = (const float*)d_in[9];   // (B,H,W,3)
    // d_in[10] = v_uvz: dead code in reference
    const float* fuvz     = (const float*)d_in[11];  // (B,F,3,3)

    int V   = in_sizes[0] / 3;
    int F   = in_sizes[3] / 3;
    int B   = in_sizes[6] / 16;
    int BHW = in_sizes[7];
    int HW  = BHW / B;
    int BF  = B * F;

    int prep_total = V + BF;
    prep_kernel<<<(prep_total + 255) / 256, 256>>>(vertices, vn, fuvz, V, BF);
    pack_kernel<<<(F + PF - 1) / PF, 256>>>(vt, f_vt, f_vn, f_v, F);
    raster_main_kernel<<<(BHW + BLK - 1) / BLK, BLK>>>(fim, depth, wm, pose,
                                                       (float*)d_out, HW, F, BHW);
}

// round 12
// speedup vs baseline: 1.4301x; 1.0145x over previous
#include <cuda_runtime.h>
#include <cuda_fp16.h>
#include <math.h>

// Fixed problem shape: F=200000, B=4, V=100000.
#define FMAX 200000
#define BMAX 4
#define VMAX 100000

// Mixed-precision 64B per-face record (4 uint4 chunks), 128B-array-aligned.
// bytes  0..23 : vt as fp32  [vt0.u vt0.v vt1.u vt1.v vt2.u vt2.v]
// bytes 24..41 : vn as fp16  [vn0.xyz vn1.xyz vn2.xyz]   (half idx 12..20)
// bytes 42..59 : v  as fp16  [v0.xyz  v1.xyz  v2.xyz ]   (half idx 21..29)
// bytes 60..63 : pad                                      (half idx 30..31)
__device__ __align__(128) uint4 g_packed[FMAX * 4];
// Per (b,f): {1/z0, 1/z1, 1/z2, 0} fp32
__device__ float4 g_invfz[BMAX * FMAX];
// fp32-expanded vertex attribute tables (one LDG.128 per gather in pack)
__device__ float4 g_verts4[VMAX];
__device__ float4 g_vns4[VMAX];

// ---------- pass 1: expand verts/vns to float4 (tiny, streaming) ----------
__global__ __launch_bounds__(256) void expand_kernel(
        const float* __restrict__ verts,
        const float* __restrict__ vns, int V) {
    int i = blockIdx.x * 256 + threadIdx.x;
    if (i >= V) return;
    g_verts4[i] = make_float4(__ldcs(&verts[3 * i]), __ldcs(&verts[3 * i + 1]),
                              __ldcs(&verts[3 * i + 2]), 0.0f);
    g_vns4[i]   = make_float4(__ldcs(&vns[3 * i]), __ldcs(&vns[3 * i + 1]),
                              __ldcs(&vns[3 * i + 2]), 0.0f);
}

// ---------- pass 2: pack records CONCURRENT WITH fz-prep (block dispatch) ----
// Blocks [0, blocksF): pack 64 faces each (L1 gather bound).
// Blocks [blocksF, blocksF+blocksFZ): invfz streaming (DRAM + MUFU bound).
#define PF 64
__global__ __launch_bounds__(256) void pack_fz_kernel(
        const float* __restrict__ vts,
        const int* __restrict__ f_vt,
        const int* __restrict__ f_vn,
        const int* __restrict__ f_v,
        const float* __restrict__ fuvz,
        int F, int blocksF, int BF) {
    int tid = threadIdx.x;
    if ((int)blockIdx.x < blocksF) {
        __shared__ float s_f[PF * 16];           // PF x 64B records
        int fbase = blockIdx.x * PF;
        if (tid < PF * 3) {
            int gi = fbase * 3 + tid;            // coalesced corner index
            int fl = tid / 3, k = tid - fl * 3;
            bool ok = (fbase + fl) < F;
            int it  = ok ? __ldg(&f_vt[gi]) : 0;
            int in_ = ok ? __ldg(&f_vn[gi]) : 0;
            int iv  = ok ? __ldg(&f_v[gi])  : 0;
            float2 t2 = __ldg((const float2*)vts + it);
            float4 n4 = __ldg(&g_vns4[in_]);
            float4 v4 = __ldg(&g_verts4[iv]);
            float*  rf = s_f + fl * 16;
            __half* rh = (__half*)rf;
            rf[2 * k + 0] = t2.x;
            rf[2 * k + 1] = t2.y;
            rh[12 + 3 * k + 0] = __float2half_rn(n4.x);
            rh[12 + 3 * k + 1] = __float2half_rn(n4.y);
            rh[12 + 3 * k + 2] = __float2half_rn(n4.z);
            rh[21 + 3 * k + 0] = __float2half_rn(v4.x);
            rh[21 + 3 * k + 1] = __float2half_rn(v4.y);
            rh[21 + 3 * k + 2] = __float2half_rn(v4.z);
            if (k == 0) { rh[30] = __float2half_rn(0.f); rh[31] = __float2half_rn(0.f); }
        }
        __syncthreads();
        const uint4* s4 = (const uint4*)s_f;
        size_t di = (size_t)fbase * 4 + tid;     // PF*4 = 256 chunks/block
        if (di < (size_t)FMAX * 4)
            g_packed[di] = s4[tid];
    } else {
        int j = ((int)blockIdx.x - blocksF) * 256 + tid;
        if (j >= BF) return;
        const float* sp = fuvz + (size_t)j * 9;
        float4 o;
        o.x = 1.0f / __ldcs(&sp[2]);
        o.y = 1.0f / __ldcs(&sp[5]);
        o.z = 1.0f / __ldcs(&sp[8]);
        o.w = 0.0f;
        g_invfz[j] = o;
    }
}

// ---------- pass 3: main per-pixel pass ----------
#define BLK 256

__global__ __launch_bounds__(BLK) void raster_main_kernel(
        const int* __restrict__ fidx_map,
        const float* __restrict__ depth,
        const float* __restrict__ weight,
        const float* __restrict__ pose,
        float* __restrict__ out,
        int HW, int F, int total) {
    __shared__ float sm[BLK * 14];

    int tid = threadIdx.x;
    int gid = blockIdx.x * BLK + tid;
    bool active = (gid < total);
    int b = (blockIdx.x * BLK) / HW;          // uniform per block (BLK | HW)

    float vals[14];
#pragma unroll
    for (int j = 0; j < 14; j++) vals[j] = 0.0f;

    if (active) {
        int f = __ldcs(&fidx_map[gid]);
        float d  = __ldcs(&depth[gid]);
        float w0 = __ldcs(&weight[gid * 3 + 0]);
        float w1 = __ldcs(&weight[gid * 3 + 1]);
        float w2 = __ldcs(&weight[gid * 3 + 2]);

        // 5 divergent gathers total: iz + 4 record chunks.
        float4 iz = __ldg(&g_invfz[b * F + f]);
        const uint4* rec4 = g_packed + (size_t)f * 4;
        uint4 q0 = __ldg(&rec4[0]);
        uint4 q1 = __ldg(&rec4[1]);
        uint4 q2 = __ldg(&rec4[2]);
        uint4 q3 = __ldg(&rec4[3]);

        // fp32 vt: words 0..5 of record
        float vt00 = __uint_as_float(q0.x);
        float vt01 = __uint_as_float(q0.y);
        float vt10 = __uint_as_float(q0.z);
        float vt11 = __uint_as_float(q0.w);
        float vt20 = __uint_as_float(q1.x);
        float vt21 = __uint_as_float(q1.y);

        // fp16 vn + v: words 6..15 -> 20 halves (18 used)
        float h[20];
        {
            unsigned int w[10] = {q1.z, q1.w,
                                  q2.x, q2.y, q2.z, q2.w,
                                  q3.x, q3.y, q3.z, q3.w};
#pragma unroll
            for (int i = 0; i < 10; i++) {
                float2 f2 = __half22float2(*(const __half2*)&w[i]);
                h[2 * i] = f2.x; h[2 * i + 1] = f2.y;
            }
        }
        // h[0..8]  = vn0.xyz vn1.xyz vn2.xyz
        // h[9..17] = v0.xyz  v1.xyz  v2.xyz

        float c0 = iz.x * w0 * d;
        float c1 = iz.y * w1 * d;
        float c2 = iz.z * w2 * d;

        // uv (full fp32)
        float u = vt00 * c0 + vt10 * c1 + vt20 * c2;
        float v = vt01 * c0 + vt11 * c1 + vt21 * c2;
        u = u - floorf(u);
        v = v - floorf(v);

        // normal blend + normalize
        float nx = h[0] * c0 + h[3] * c1 + h[6] * c2;
        float ny = h[1] * c0 + h[4] * c1 + h[7] * c2;
        float nz = h[2] * c0 + h[5] * c1 + h[8] * c2;
        float nl = sqrtf(nx * nx + ny * ny + nz * nz);
        float inl = 1.0f / fmaxf(nl, 1e-12f);
        float Nx = nx * inl, Ny = ny * inl, Nz = nz * inl;

        // position blend
        float px = h[9]  * c0 + h[12] * c1 + h[15] * c2;
        float py = h[10] * c0 + h[13] * c1 + h[16] * c2;
        float pz = h[11] * c0 + h[14] * c1 + h[17] * c2;

        // pose (b block-uniform -> broadcast loads)
        const float* P = pose + b * 16;
        float R00 = __ldg(&P[0]), R01 = __ldg(&P[1]), R02 = __ldg(&P[2]),  t0 = __ldg(&P[3]);
        float R10 = __ldg(&P[4]), R11 = __ldg(&P[5]), R12 = __ldg(&P[6]),  t1 = __ldg(&P[7]);
        float R20 = __ldg(&P[8]), R21 = __ldg(&P[9]), R22 = __ldg(&P[10]), t2 = __ldg(&P[11]);

        float mx = R00 * Nx + R01 * Ny + R02 * Nz;
        float my = R10 * Nx + R11 * Ny + R12 * Nz;
        float mz = R20 * Nx + R21 * Ny + R22 * Nz;
        float ml = sqrtf(mx * mx + my * my + mz * mz);
        float iml = 1.0f / fmaxf(ml, 1e-12f);
        mx *= iml; my *= iml; mz *= iml;

        float qx = R00 * px + R01 * py + R02 * pz + t0;
        float qy = R10 * px + R11 * py + R12 * pz + t1;
        float qz = R20 * px + R12 == R12 ? R21 * py : R21 * py; // placeholder avoided
        qz = R20 * px + R21 * py + R22 * pz + t2;

        vals[0] = u;   vals[1] = v;
        vals[2] = Nx;  vals[3] = Ny;  vals[4] = Nz;
        vals[5] = mx;  vals[6] = my;  vals[7] = mz;
        vals[8] = px;  vals[9] = py;  vals[10] = pz;
        vals[11] = qx; vals[12] = qy; vals[13] = qz;
    }

    // Stage to smem, then coalesced float4 streaming stores.
#pragma unroll
    for (int j = 0; j < 14; j++) sm[tid * 14 + j] = vals[j];
    __syncthreads();

    size_t blk_base = (size_t)blockIdx.x * BLK * 14;
    const float4* sm4 = (const float4*)sm;
    float4* out4 = (float4*)(out + blk_base);
    int nfloat4 = (BLK * 14) / 4;                      // 896
    size_t limit4 = ((size_t)total * 14 - blk_base) / 4;
#pragma unroll
    for (int idx = 0; idx < nfloat4 / BLK + 1; idx++) {
        int e = idx * BLK + tid;
        if (e < nfloat4 && (size_t)e < limit4)
            __stcs(&out4[e], sm4[e]);
    }
}

extern "C" void kernel_launch(void* const* d_in, const int* in_sizes, int n_in,
                              void* d_out, int out_size) {
    const float* vertices = (const float*)d_in[0];   // (1,V,3)
    const float* vt       = (const float*)d_in[1];   // (1,V,2)
    const float* vn       = (const float*)d_in[2];   // (1,V,3)
    const int*   f_vt     = (const int*)d_in[3];     // (1,F,3)
    const int*   f_vn     = (const int*)d_in[4];     // (1,F,3)
    const int*   f_v      = (const int*)d_in[5];     // (1,F,3)
    const float* pose     = (const float*)d_in[6];   // (B,4,4)
    const float* depth    = (const float*)d_in[7];   // (B,H,W)
    const int*   fim      = (const int*)d_in[8];     // (B,H,W)
    const float* wm       = (const float*)d_in[9];   // (B,H,W,3)
    // d_in[10] = v_uvz: dead code in reference
    const float* fuvz     = (const float*)d_in[11];  // (B,F,3,3)

    int V   = in_sizes[0] / 3;
    int F   = in_sizes[3] / 3;
    int B   = in_sizes[6] / 16;
    int BHW = in_sizes[7];
    int HW  = BHW / B;
    int BF  = B * F;

    int blocksF  = (F + PF - 1) / PF;
    int blocksFZ = (BF + 255) / 256;

    expand_kernel<<<(V + 255) / 256, 256>>>(vertices, vn, V);
    pack_fz_kernel<<<blocksF + blocksFZ, 256>>>(vt, f_vt, f_vn, f_v, fuvz,
                                                F, blocksF, BF);
    raster_main_kernel<<<(BHW + BLK - 1) / BLK, BLK>>>(fim, depth, wm, pose,
                                                       (float*)d_out, HW, F, BHW);
}

// round 13
// speedup vs baseline: 1.4701x; 1.0280x over previous
#include <cuda_runtime.h>
#include <cuda_fp16.h>
#include <math.h>

// Fixed problem shape: F=200000, B=4, V=100000.
#define FMAX 200000
#define BMAX 4
#define VMAX 100000

// Mixed-precision 64B per-face record (4 uint4 chunks), 128B-array-aligned.
// bytes  0..23 : vt as fp32  [vt0.u vt0.v vt1.u vt1.v vt2.u vt2.v]
// bytes 24..41 : vn as fp16  [vn0.xyz vn1.xyz vn2.xyz]   (half idx 12..20)
// bytes 42..59 : v  as fp16  [v0.xyz  v1.xyz  v2.xyz ]   (half idx 21..29)
// bytes 60..63 : pad                                      (half idx 30..31)
__device__ __align__(128) uint4 g_packed[FMAX * 4];
// Per (b,f): {1/z0, 1/z1, 1/z2, 0} fp32
__device__ float4 g_invfz[BMAX * FMAX];
// fp32-expanded vertex attribute tables (one LDG.128 per gather in pack)
__device__ float4 g_verts4[VMAX];
__device__ float4 g_vns4[VMAX];

// ---------- pass 1: expand verts/vns to float4 (tiny, streaming) ----------
__global__ __launch_bounds__(256) void expand_kernel(
        const float* __restrict__ verts,
        const float* __restrict__ vns, int V) {
    int i = blockIdx.x * 256 + threadIdx.x;
    if (i >= V) return;
    g_verts4[i] = make_float4(__ldcs(&verts[3 * i]), __ldcs(&verts[3 * i + 1]),
                              __ldcs(&verts[3 * i + 2]), 0.0f);
    g_vns4[i]   = make_float4(__ldcs(&vns[3 * i]), __ldcs(&vns[3 * i + 1]),
                              __ldcs(&vns[3 * i + 2]), 0.0f);
}

// ---------- pass 2: pack (L1-bound) INTERLEAVED with fz (DRAM-bound) --------
// Parity-interleaved block dispatch so both kinds are co-resident from wave 1.
#define PF 64
__global__ __launch_bounds__(256) void pack_fz_kernel(
        const float* __restrict__ vts,
        const int* __restrict__ f_vt,
        const int* __restrict__ f_vn,
        const int* __restrict__ f_v,
        const float* __restrict__ fuvz,
        int F, int blocksF, int blocksFZ, int BF) {
    int tid = threadIdx.x;
    int bi  = blockIdx.x;
    // parity interleave, generalized for unequal counts
    int twice = 2 * (blocksF < blocksFZ ? blocksF : blocksFZ);
    bool isPack;
    int idx;
    if (bi < twice) { isPack = !(bi & 1); idx = bi >> 1; }
    else {
        int r = bi - twice;
        if (blocksF > blocksFZ) { isPack = true;  idx = blocksFZ + r; }
        else                    { isPack = false; idx = blocksF  + r; }
    }

    if (isPack) {
        __shared__ float s_f[PF * 16];           // PF x 64B records
        int fbase = idx * PF;
        if (tid < PF * 3) {
            int gi = fbase * 3 + tid;            // coalesced corner index
            int fl = tid / 3, k = tid - fl * 3;
            bool ok = (fbase + fl) < F;
            int it  = ok ? __ldg(&f_vt[gi]) : 0;
            int in_ = ok ? __ldg(&f_vn[gi]) : 0;
            int iv  = ok ? __ldg(&f_v[gi])  : 0;
            float2 t2 = __ldg((const float2*)vts + it);
            float4 n4 = __ldg(&g_vns4[in_]);
            float4 v4 = __ldg(&g_verts4[iv]);
            float*  rf = s_f + fl * 16;
            __half* rh = (__half*)rf;
            rf[2 * k + 0] = t2.x;
            rf[2 * k + 1] = t2.y;
            rh[12 + 3 * k + 0] = __float2half_rn(n4.x);
            rh[12 + 3 * k + 1] = __float2half_rn(n4.y);
            rh[12 + 3 * k + 2] = __float2half_rn(n4.z);
            rh[21 + 3 * k + 0] = __float2half_rn(v4.x);
            rh[21 + 3 * k + 1] = __float2half_rn(v4.y);
            rh[21 + 3 * k + 2] = __float2half_rn(v4.z);
            if (k == 0) { rh[30] = __float2half_rn(0.f); rh[31] = __float2half_rn(0.f); }
        }
        __syncthreads();
        const uint4* s4 = (const uint4*)s_f;
        size_t di = (size_t)fbase * 4 + tid;     // PF*4 = 256 chunks/block
        if (di < (size_t)FMAX * 4)
            g_packed[di] = s4[tid];
    } else {
        int j = idx * 256 + tid;
        if (j >= BF) return;
        const float* sp = fuvz + (size_t)j * 9;
        float4 o;
        o.x = 1.0f / __ldcs(&sp[2]);
        o.y = 1.0f / __ldcs(&sp[5]);
        o.z = 1.0f / __ldcs(&sp[8]);
        o.w = 0.0f;
        g_invfz[j] = o;
    }
}

// ---------- pass 3: main per-pixel pass (2 pixels/thread, batched loads) ----
#define BLK 128
#define PPB 256   // pixels per block

__global__ __launch_bounds__(BLK) void raster_main_kernel(
        const int* __restrict__ fidx_map,
        const float* __restrict__ depth,
        const float* __restrict__ weight,
        const float* __restrict__ pose,
        float* __restrict__ out,
        int HW, int F, int total) {
    __shared__ float sm[PPB * 14];

    int tid  = threadIdx.x;
    int base = blockIdx.x * PPB;
    int b    = base / HW;                     // uniform per block (PPB | HW)

    // pose once per thread (broadcast loads)
    const float* P = pose + b * 16;
    float R00 = __ldg(&P[0]), R01 = __ldg(&P[1]), R02 = __ldg(&P[2]),  t0 = __ldg(&P[3]);
    float R10 = __ldg(&P[4]), R11 = __ldg(&P[5]), R12 = __ldg(&P[6]),  t1 = __ldg(&P[7]);
    float R20 = __ldg(&P[8]), R21 = __ldg(&P[9]), R22 = __ldg(&P[10]), t2 = __ldg(&P[11]);

    // ---- front-batched loads for both pixels (max MLP) ----
    int   gid[2];
    bool  act[2];
    int   f[2];
    float d[2], w0[2], w1[2], w2[2];
    float4 iz[2];
    uint4 q0[2], q1[2], q2[2], q3[2];

#pragma unroll
    for (int s = 0; s < 2; s++) {
        gid[s] = base + s * BLK + tid;
        act[s] = (gid[s] < total);
        int g = act[s] ? gid[s] : 0;
        f[s]  = __ldcs(&fidx_map[g]);
        d[s]  = __ldcs(&depth[g]);
        w0[s] = __ldcs(&weight[g * 3 + 0]);
        w1[s] = __ldcs(&weight[g * 3 + 1]);
        w2[s] = __ldcs(&weight[g * 3 + 2]);
    }
#pragma unroll
    for (int s = 0; s < 2; s++) {
        iz[s] = __ldg(&g_invfz[b * F + f[s]]);
        const uint4* rec4 = g_packed + (size_t)f[s] * 4;
        q0[s] = __ldg(&rec4[0]);
        q1[s] = __ldg(&rec4[1]);
        q2[s] = __ldg(&rec4[2]);
        q3[s] = __ldg(&rec4[3]);
    }

    // ---- compute + smem staging ----
#pragma unroll
    for (int s = 0; s < 2; s++) {
        float vals[14];
#pragma unroll
        for (int j = 0; j < 14; j++) vals[j] = 0.0f;

        if (act[s]) {
            // fp32 vt: words 0..5
            float vt00 = __uint_as_float(q0[s].x);
            float vt01 = __uint_as_float(q0[s].y);
            float vt10 = __uint_as_float(q0[s].z);
            float vt11 = __uint_as_float(q0[s].w);
            float vt20 = __uint_as_float(q1[s].x);
            float vt21 = __uint_as_float(q1[s].y);

            // fp16 vn + v: words 6..15 -> 20 halves (18 used)
            float h[20];
            {
                unsigned int w[10] = {q1[s].z, q1[s].w,
                                      q2[s].x, q2[s].y, q2[s].z, q2[s].w,
                                      q3[s].x, q3[s].y, q3[s].z, q3[s].w};
#pragma unroll
                for (int i = 0; i < 10; i++) {
                    float2 f2 = __half22float2(*(const __half2*)&w[i]);
                    h[2 * i] = f2.x; h[2 * i + 1] = f2.y;
                }
            }

            float c0 = iz[s].x * w0[s] * d[s];
            float c1 = iz[s].y * w1[s] * d[s];
            float c2 = iz[s].z * w2[s] * d[s];

            // uv (full fp32)
            float u = vt00 * c0 + vt10 * c1 + vt20 * c2;
            float v = vt01 * c0 + vt11 * c1 + vt21 * c2;
            u = u - floorf(u);
            v = v - floorf(v);

            // normal blend + normalize
            float nx = h[0] * c0 + h[3] * c1 + h[6] * c2;
            float ny = h[1] * c0 + h[4] * c1 + h[7] * c2;
            float nz = h[2] * c0 + h[5] * c1 + h[8] * c2;
            float nl = sqrtf(nx * nx + ny * ny + nz * nz);
            float inl = 1.0f / fmaxf(nl, 1e-12f);
            float Nx = nx * inl, Ny = ny * inl, Nz = nz * inl;

            // position blend
            float px = h[9]  * c0 + h[12] * c1 + h[15] * c2;
            float py = h[10] * c0 + h[13] * c1 + h[16] * c2;
            float pz = h[11] * c0 + h[14] * c1 + h[17] * c2;

            float mx = R00 * Nx + R01 * Ny + R02 * Nz;
            float my = R10 * Nx + R11 * Ny + R12 * Nz;
            float mz = R20 * Nx + R21 * Ny + R22 * Nz;
            float ml = sqrtf(mx * mx + my * my + mz * mz);
            float iml = 1.0f / fmaxf(ml, 1e-12f);
            mx *= iml; my *= iml; mz *= iml;

            float qx = R00 * px + R01 * py + R02 * pz + t0;
            float qy = R10 * px + R11 * py + R12 * pz + t1;
            float qz = R20 * px + R21 * py + R22 * pz + t2;

            vals[0] = u;   vals[1] = v;
            vals[2] = Nx;  vals[3] = Ny;  vals[4] = Nz;
            vals[5] = mx;  vals[6] = my;  vals[7] = mz;
            vals[8] = px;  vals[9] = py;  vals[10] = pz;
            vals[11] = qx; vals[12] = qy; vals[13] = qz;
        }

        int slot = s * BLK + tid;
#pragma unroll
        for (int j = 0; j < 14; j++) sm[slot * 14 + j] = vals[j];
    }
    __syncthreads();

    // coalesced float4 streaming stores of the block's contiguous region
    size_t blk_base = (size_t)blockIdx.x * PPB * 14;
    const float4* sm4 = (const float4*)sm;
    float4* out4 = (float4*)(out + blk_base);
    int nfloat4 = (PPB * 14) / 4;                      // 896
    size_t limit4 = ((size_t)total * 14 - blk_base) / 4;
#pragma unroll
    for (int it = 0; it < 7; it++) {
        int e = it * BLK + tid;
        if (e < nfloat4 && (size_t)e < limit4)
            __stcs(&out4[e], sm4[e]);
    }
}

extern "C" void kernel_launch(void* const* d_in, const int* in_sizes, int n_in,
                              void* d_out, int out_size) {
    const float* vertices = (const float*)d_in[0];   // (1,V,3)
    const float* vt       = (const float*)d_in[1];   // (1,V,2)
    const float* vn       = (const float*)d_in[2];   // (1,V,3)
    const int*   f_vt     = (const int*)d_in[3];     // (1,F,3)
    const int*   f_vn     = (const int*)d_in[4];     // (1,F,3)
    const int*   f_v      = (const int*)d_in[5];     // (1,F,3)
    const float* pose     = (const float*)d_in[6];   // (B,4,4)
    const float* depth    = (const float*)d_in[7];   // (B,H,W)
    const int*   fim      = (const int*)d_in[8];     // (B,H,W)
    const float* wm       = (const float*)d_in[9];   // (B,H,W,3)
    // d_in[10] = v_uvz: dead code in reference
    const float* fuvz     = (const float*)d_in[11];  // (B,F,3,3)

    int V   = in_sizes[0] / 3;
    int F   = in_sizes[3] / 3;
    int B   = in_sizes[6] / 16;
    int BHW = in_sizes[7];
    int HW  = BHW / B;
    int BF  = B * F;

    int blocksF  = (F + PF - 1) / PF;
    int blocksFZ = (BF + 255) / 256;

    expand_kernel<<<(V + 255) / 256, 256>>>(vertices, vn, V);
    pack_fz_kernel<<<blocksF + blocksFZ, 256>>>(vt, f_vt, f_vn, f_v, fuvz,
                                                F, blocksF, blocksFZ, BF);
    raster_main_kernel<<<(BHW + PPB - 1) / PPB, BLK>>>(fim, depth, wm, pose,
                                                       (float*)d_out, HW, F, BHW);
}